// round 16
// baseline (speedup 1.0000x reference)
#include <cuda_runtime.h>
#include <cuda_fp16.h>
#include <math.h>
#include <stdint.h>

#define BB 64
#define VV 197
#define LL 64
#define DD 768
#define EE 256

// Scratch: projected + normalized tokens in fp16, transposed half weights
__device__ __align__(16) __half g_vtok[(size_t)BB * VV * EE]; // 6.45 MB
__device__ __align__(16) __half g_ttok[(size_t)BB * LL * EE]; // 2.1 MB
__device__ __align__(16) __half g_wvtT[(size_t)EE * DD];      // [n][k]
__device__ __align__(16) __half g_wttT[(size_t)EE * DD];

// ---------------------------------------------------------------------------
// helpers
// ---------------------------------------------------------------------------
__device__ __forceinline__ void mma16(float* c, unsigned a0, unsigned a1, unsigned a2,
                                      unsigned a3, unsigned b0, unsigned b1) {
    asm volatile(
        "mma.sync.aligned.m16n8k16.row.col.f32.f16.f16.f32 "
        "{%0,%1,%2,%3},{%4,%5,%6,%7},{%8,%9},{%0,%1,%2,%3};\n"
        : "+f"(c[0]), "+f"(c[1]), "+f"(c[2]), "+f"(c[3])
        : "r"(a0), "r"(a1), "r"(a2), "r"(a3), "r"(b0), "r"(b1));
}

__device__ __forceinline__ void cpa16(unsigned s, const void* g) {
    asm volatile("cp.async.cg.shared.global [%0], [%1], 16;" :: "r"(s), "l"(g) : "memory");
}
__device__ __forceinline__ void cpa_commit() {
    asm volatile("cp.async.commit_group;" ::: "memory");
}
__device__ __forceinline__ void cpa_wait0() {
    asm volatile("cp.async.wait_group 0;" ::: "memory");
}
__device__ __forceinline__ unsigned s2u(const void* p) {
    return (unsigned)__cvta_generic_to_shared(p);
}

// ---------------------------------------------------------------------------
// W transpose + fp32->fp16 prepass: W[768][256] -> WT[256][768] half.
// Only the TOKEN weights (Wvt, Wtt) — cls weights are handled in-proj.
// grid (24, 8, 2), block (32, 8). z: 0=Wvt 1=Wtt.
// ---------------------------------------------------------------------------
__global__ void wprep_kernel(const float* __restrict__ Wvt, const float* __restrict__ Wtt,
                             __half* __restrict__ WvtT, __half* __restrict__ WttT)
{
    cudaTriggerProgrammaticLaunchCompletion();

    __shared__ float t[32][33];
    const float* W = blockIdx.z ? Wtt : Wvt;
    __half* WT = blockIdx.z ? WttT : WvtT;
    int kb = blockIdx.x * 32, nb = blockIdx.y * 32;
    int tx = threadIdx.x, ty = threadIdx.y;
    #pragma unroll
    for (int j = 0; j < 4; j++)
        t[ty + 8 * j][tx] = W[(size_t)(kb + ty + 8 * j) * EE + nb + tx];
    __syncthreads();
    #pragma unroll
    for (int j = 0; j < 4; j++)
        WT[(size_t)(nb + ty + 8 * j) * DD + kb + tx] = __float2half(t[tx][ty + 8 * j]);
}

// ---------------------------------------------------------------------------
// Unified projection (fp16 MMA m16n8k16, fp32 accum), 2 blocks/SM.
// Token blocks [0,261): WT via cp.async (depends on wprep; PDL grid-dep sync
// after a W-independent A-chunk-0 prefill). cls blocks 261/262: read fp32
// Wv/Wt directly, convert in-register into [k][n] smem — no wprep dependency,
// no grid-dep sync.
// ---------------------------------------------------------------------------
__global__ __launch_bounds__(256, 2) void proj_kernel(
    const float* __restrict__ visual_cls, const float* __restrict__ textual_cls,
    const float* __restrict__ vtokA, const float* __restrict__ ttokA,
    const float* __restrict__ bv, const float* __restrict__ bt,
    const float* __restrict__ bvt, const float* __restrict__ btt,
    const __half* __restrict__ WvtT, const __half* __restrict__ WttT,
    const float* __restrict__ Wv32, const float* __restrict__ Wt32,
    float* __restrict__ out, __half* __restrict__ vtokC, __half* __restrict__ ttokC)
{
    cudaTriggerProgrammaticLaunchCompletion();

    extern __shared__ float sm[];
    __shared__ float sbias[256];
    __shared__ float rowsq[64 * 5];
    __shared__ float sinv[64];

    __half* sAh = (__half*)sm;               // 64 x 136

    const int bid = blockIdx.x;
    const int tid = threadIdx.x;
    const int lane = tid & 31, w = tid >> 5;
    const int lq = lane >> 2, lr = lane & 3;
    const int vg = w >> 2, nw = w & 3;
    const int rbase = vg * 32;
    const int nb = nw * 64;

    // =======================================================================
    // cls path (blocks 261/262): fp32 W read + in-register convert.
    // Reads ONLY kernel inputs -> no wprep dependency, no grid-dep sync.
    // =======================================================================
    if (bid >= 261) {
        const float* A   = (bid == 261) ? visual_cls : textual_cls;
        const float* W32 = (bid == 261) ? Wv32 : Wt32;
        const float* bias = (bid == 261) ? bv : bt;
        float* Cf = out + (bid == 261 ? 0 : 16384);

        __half* sWc = (__half*)sm + 64 * 136;    // 128 x 264 ([k][n] layout)
        sbias[tid] = bias[tid];

        float acc[2][8][4] = {};

        for (int k0 = 0; k0 < DD; k0 += 128) {
            // W chunk: 128 k-rows x 256 n fp32 -> half smem [k][n]
            #pragma unroll
            for (int it = 0; it < 32; it++) {
                int idx = tid + it * 256;        // 0..8191
                int r = idx >> 6;                // k row 0..127
                int c4 = idx & 63;               // float4 along n
                float4 v = *(const float4*)(W32 + (size_t)(k0 + r) * EE + c4 * 4);
                __half2 h0 = __floats2half2_rn(v.x, v.y);
                __half2 h1 = __floats2half2_rn(v.z, v.w);
                uint2 pk = make_uint2(*(unsigned*)&h0, *(unsigned*)&h1);
                *(uint2*)(sWc + r * 264 + c4 * 4) = pk;
            }
            // A chunk: 64 rows x 128 k fp32 -> half
            #pragma unroll
            for (int it = 0; it < 8; it++) {
                int idx = tid + it * 256;
                int r = idx >> 5;
                int c4 = idx & 31;
                float4 v = *(const float4*)(A + (size_t)r * DD + k0 + c4 * 4);
                __half2 h0 = __floats2half2_rn(v.x, v.y);
                __half2 h1 = __floats2half2_rn(v.z, v.w);
                uint2 pk = make_uint2(*(unsigned*)&h0, *(unsigned*)&h1);
                *(uint2*)(sAh + r * 136 + c4 * 4) = pk;
            }
            __syncthreads();

            #pragma unroll
            for (int ks = 0; ks < 8; ks++) {
                unsigned b0[8], b1[8];
                int kk = ks * 16 + 2 * lr;
                #pragma unroll
                for (int ng = 0; ng < 8; ng++) {
                    const __half* pc = sWc + kk * 264 + nb + 8 * ng + lq;
                    unsigned lo = *(const unsigned short*)pc;
                    unsigned hi = *(const unsigned short*)(pc + 264);
                    b0[ng] = lo | (hi << 16);
                    lo = *(const unsigned short*)(pc + 8 * 264);
                    hi = *(const unsigned short*)(pc + 9 * 264);
                    b1[ng] = lo | (hi << 16);
                }
                #pragma unroll
                for (int rg = 0; rg < 2; rg++) {
                    const __half* p = sAh + (rbase + 16 * rg + lq) * 136 + ks * 16 + 2 * lr;
                    unsigned a0 = *(const unsigned*)p;
                    unsigned a1 = *(const unsigned*)(p + 8 * 136);
                    unsigned a2 = *(const unsigned*)(p + 8);
                    unsigned a3 = *(const unsigned*)(p + 8 * 136 + 8);
                    #pragma unroll
                    for (int ng = 0; ng < 8; ng++)
                        mma16(acc[rg][ng], a0, a1, a2, a3, b0[ng], b1[ng]);
                }
            }
            __syncthreads();
        }

        #pragma unroll
        for (int rg = 0; rg < 2; rg++) {
            int r0 = rbase + 16 * rg + lq;
            #pragma unroll
            for (int ng = 0; ng < 8; ng++) {
                int col = nb + 8 * ng + 2 * lr;
                float c0 = sbias[col], c1 = sbias[col + 1];
                *(float2*)(Cf + (size_t)r0 * EE + col) =
                    make_float2(acc[rg][ng][0] + c0, acc[rg][ng][1] + c1);
                *(float2*)(Cf + (size_t)(r0 + 8) * EE + col) =
                    make_float2(acc[rg][ng][2] + c0, acc[rg][ng][3] + c1);
            }
        }
        return;
    }

    // =======================================================================
    // Token path (blocks [0,261)): WT via cp.async, fused bias + l2norm.
    // =======================================================================
    __half* sWh = (__half*)sm + 64 * 136;    // 256 x 136

    const float* A;
    const __half* WT;
    const float* bias;
    __half* C;
    int mbase;
    if (bid < 197) { A = vtokA; WT = WvtT; bias = bvt; C = vtokC; mbase = bid * 64; }
    else           { A = ttokA; WT = WttT; bias = btt; C = ttokC; mbase = (bid - 197) * 64; }

    sbias[tid] = bias[tid];

    const unsigned sWu = s2u(sWh);

    // Prefill A chunk 0 (reads only input tokens — independent of wprep)
    #pragma unroll
    for (int it = 0; it < 8; it++) {
        int idx = tid + it * 256;        // 0..2047
        int r = idx >> 5;                // 0..63
        int c4 = idx & 31;               // float4 unit along k
        float4 v = *(const float4*)(A + (size_t)(mbase + r) * DD + c4 * 4);
        __half2 h0 = __floats2half2_rn(v.x, v.y);
        __half2 h1 = __floats2half2_rn(v.z, v.w);
        uint2 pk = make_uint2(*(unsigned*)&h0, *(unsigned*)&h1);
        *(uint2*)(sAh + r * 136 + c4 * 4) = pk;
    }

    // Wait for wprep's WT to be complete + visible
    cudaGridDependencySynchronize();

    float acc[2][8][4] = {};

    for (int k0 = 0; k0 < DD; k0 += 128) {
        // W chunk: 256 n-rows x 128 k halves via cp.async (16 x 16B per row)
        #pragma unroll
        for (int it = 0; it < 16; it++) {
            int idx = tid + it * 256;        // 0..4095
            int r = idx >> 4;                // 0..255
            int c16 = idx & 15;              // 16-byte chunk (8 halves)
            cpa16(sWu + (unsigned)(r * 136 + c16 * 8) * 2,
                  WT + (size_t)r * DD + k0 + c16 * 8);
        }
        cpa_commit();
        // A chunk: 64 rows x 128 k, fp32 -> half in-register (chunk 0 prefilled)
        if (k0 > 0) {
            #pragma unroll
            for (int it = 0; it < 8; it++) {
                int idx = tid + it * 256;
                int r = idx >> 5;
                int c4 = idx & 31;
                float4 v = *(const float4*)(A + (size_t)(mbase + r) * DD + k0 + c4 * 4);
                __half2 h0 = __floats2half2_rn(v.x, v.y);
                __half2 h1 = __floats2half2_rn(v.z, v.w);
                uint2 pk = make_uint2(*(unsigned*)&h0, *(unsigned*)&h1);
                *(uint2*)(sAh + r * 136 + c4 * 4) = pk;
            }
        }
        cpa_wait0();
        __syncthreads();

        #pragma unroll
        for (int ks = 0; ks < 8; ks++) {
            unsigned b0[8], b1[8];
            #pragma unroll
            for (int ng = 0; ng < 8; ng++) {
                const __half* p = sWh + (nb + 8 * ng + lq) * 136 + ks * 16 + 2 * lr;
                b0[ng] = *(const unsigned*)p;
                b1[ng] = *(const unsigned*)(p + 8);
            }
            #pragma unroll
            for (int rg = 0; rg < 2; rg++) {
                const __half* p = sAh + (rbase + 16 * rg + lq) * 136 + ks * 16 + 2 * lr;
                unsigned a0 = *(const unsigned*)p;
                unsigned a1 = *(const unsigned*)(p + 8 * 136);
                unsigned a2 = *(const unsigned*)(p + 8);
                unsigned a3 = *(const unsigned*)(p + 8 * 136 + 8);
                #pragma unroll
                for (int ng = 0; ng < 8; ng++)
                    mma16(acc[rg][ng], a0, a1, a2, a3, b0[ng], b1[ng]);
            }
        }
        __syncthreads();
    }

    // bias
    #pragma unroll
    for (int rg = 0; rg < 2; rg++)
        #pragma unroll
        for (int ng = 0; ng < 8; ng++) {
            int col = nb + 8 * ng + 2 * lr;
            float c0 = sbias[col], c1 = sbias[col + 1];
            acc[rg][ng][0] += c0; acc[rg][ng][1] += c1;
            acc[rg][ng][2] += c0; acc[rg][ng][3] += c1;
        }

    // l2norm: per-row sum of squares
    #pragma unroll
    for (int rg = 0; rg < 2; rg++) {
        float s0 = 0.f, s1 = 0.f;
        #pragma unroll
        for (int ng = 0; ng < 8; ng++) {
            s0 += acc[rg][ng][0] * acc[rg][ng][0] + acc[rg][ng][1] * acc[rg][ng][1];
            s1 += acc[rg][ng][2] * acc[rg][ng][2] + acc[rg][ng][3] * acc[rg][ng][3];
        }
        s0 += __shfl_xor_sync(0xffffffffu, s0, 1);
        s0 += __shfl_xor_sync(0xffffffffu, s0, 2);
        s1 += __shfl_xor_sync(0xffffffffu, s1, 1);
        s1 += __shfl_xor_sync(0xffffffffu, s1, 2);
        if (lr == 0) {
            rowsq[(rbase + 16 * rg + lq) * 5 + nw] = s0;
            rowsq[(rbase + 16 * rg + lq + 8) * 5 + nw] = s1;
        }
    }
    __syncthreads();
    if (tid < 64) {
        float s = rowsq[tid * 5] + rowsq[tid * 5 + 1] + rowsq[tid * 5 + 2] + rowsq[tid * 5 + 3];
        sinv[tid] = 1.0f / fmaxf(sqrtf(s), 1e-12f);
    }
    __syncthreads();

    #pragma unroll
    for (int rg = 0; rg < 2; rg++) {
        int r0 = rbase + 16 * rg + lq;
        float inv0 = sinv[r0], inv1 = sinv[r0 + 8];
        #pragma unroll
        for (int ng = 0; ng < 8; ng++) {
            int col = nb + 8 * ng + 2 * lr;
            __half2 h0 = __floats2half2_rn(acc[rg][ng][0] * inv0, acc[rg][ng][1] * inv0);
            __half2 h1 = __floats2half2_rn(acc[rg][ng][2] * inv1, acc[rg][ng][3] * inv1);
            *(__half2*)(C + (size_t)(mbase + r0) * EE + col) = h0;
            *(__half2*)(C + (size_t)(mbase + r0 + 8) * EE + col) = h1;
        }
    }
}

// ---------------------------------------------------------------------------
// Fused sim kernel (fp16 MMA m16n8k16, f32 accum).
// grid = (qpair=32, b=64), 256 threads (8 warps = 4 v-groups x 2 t-groups).
// PDL: grid-dep-syncs on proj before touching vtok/ttok. Block tile
// 128v x 128t; sT resident for K=256; sV streamed as 4 chunks with
// lookahead cp.async; m16 padding elision (rows issued 208 of 197 valid).
// ---------------------------------------------------------------------------
#define SVS 136
#define STS 264

__global__ __launch_bounds__(256, 2) void sim_kernel(
    const __half* __restrict__ vtok, const __half* __restrict__ ttok,
    const int* __restrict__ text_length, float* __restrict__ out)
{
    extern __shared__ __half smh[];
    __half* sV = smh;                  // 128 x SVS
    __half* sT = smh + 128 * SVS;      // 128 x STS (full K)

    __shared__ float t2i_part[4][128];
    __shared__ float t2i_run[128];
    __shared__ float wsum[8];

    const int tid = threadIdx.x;
    const int lane = tid & 31, w = tid >> 5;
    const int lq = lane >> 2, lr = lane & 3;
    const int vb = (w >> 1) * 32;
    const int tb = (w & 1) * 64;
    const int qp = blockIdx.x, b = blockIdx.y;

    const __half* vbase = vtok + (size_t)b * VV * EE;
    const __half* tbase = ttok + (size_t)(qp * 2) * LL * EE;

    unsigned sVu = (unsigned)__cvta_generic_to_shared(sV);
    unsigned sTu = (unsigned)__cvta_generic_to_shared(sT);

    // Wait for proj's vtok/ttok to be complete + visible
    cudaGridDependencySynchronize();

    // sT: full 128 t-rows x 256 k (once per block) + sV chunk 0
    #pragma unroll
    for (int it = 0; it < 16; it++) {
        int idx = tid + it * 256;
        int r = idx >> 5;
        int c8 = idx & 31;
        cpa16(sTu + (unsigned)(r * STS + c8 * 8) * 2, tbase + (size_t)r * EE + c8 * 8);
    }
    #pragma unroll
    for (int it = 0; it < 8; it++) {
        int idx = tid + it * 256;
        int r = idx >> 4;
        int c8 = idx & 15;
        int vr = min(r, VV - 1);
        cpa16(sVu + (unsigned)(r * SVS + c8 * 8) * 2,
              vbase + (size_t)vr * EE + c8 * 8);
    }
    cpa_commit();

    float i2t_wsum = 0.0f;
    float acc[2][8][4];

    #pragma unroll
    for (int c = 0; c < 4; ++c) {
        const int pass = c >> 1, kc = c & 1;
        const int v0 = pass * 128;
        const bool active = (v0 + vb) < VV;
        const bool rgok0 = (v0 + vb) < VV;
        const bool rgok1 = (v0 + vb + 16) < VV;

        if (kc == 0) {
            #pragma unroll
            for (int rg = 0; rg < 2; rg++)
                #pragma unroll
                for (int ng = 0; ng < 8; ng++)
                    #pragma unroll
                    for (int j = 0; j < 4; j++) acc[rg][ng][j] = 0.0f;
        }

        cpa_wait0();
        __syncthreads();

        if (active) {
            #pragma unroll
            for (int ks = 0; ks < 8; ks++) {
                unsigned b0[8], b1[8];
                #pragma unroll
                for (int ng = 0; ng < 8; ng++) {
                    const __half* p = sT + (tb + 8 * ng + lq) * STS + kc * 128 + ks * 16 + 2 * lr;
                    b0[ng] = *(const unsigned*)p;
                    b1[ng] = *(const unsigned*)(p + 8);
                }
                #pragma unroll
                for (int rg = 0; rg < 2; rg++) {
                    if (rg == 0 ? rgok0 : rgok1) {
                        const __half* p = sV + (vb + 16 * rg + lq) * SVS + ks * 16 + 2 * lr;
                        unsigned a0 = *(const unsigned*)p;
                        unsigned a1 = *(const unsigned*)(p + 8 * SVS);
                        unsigned a2 = *(const unsigned*)(p + 8);
                        unsigned a3 = *(const unsigned*)(p + 8 * SVS + 8);
                        #pragma unroll
                        for (int ng = 0; ng < 8; ng++)
                            mma16(acc[rg][ng], a0, a1, a2, a3, b0[ng], b1[ng]);
                    }
                }
            }
        }
        __syncthreads();   // MMAs done block-wide -> sV free for next chunk

        // lookahead: issue next chunk's sV loads
        if (c < 3) {
            const int nc = c + 1;
            const int np = nc >> 1, nkc = nc & 1;
            const int nv0 = np * 128;
            const int itmax = (np == 0) ? 8 : 5;
            for (int it = 0; it < itmax; it++) {
                int idx = tid + it * 256;
                int r = idx >> 4;
                int c8 = idx & 15;
                int vr = min(nv0 + r, VV - 1);
                cpa16(sVu + (unsigned)(r * SVS + c8 * 8) * 2,
                      vbase + (size_t)vr * EE + nkc * 128 + c8 * 8);
            }
            cpa_commit();
        }

        if (kc == 1) {
            // ---- i2t: per-v-row max over this warp's 64 t cols ----
            float rsum = 0.0f;
            #pragma unroll
            for (int rg = 0; rg < 2; rg++) {
                float m0 = -1e30f, m1 = -1e30f;
                #pragma unroll
                for (int ng = 0; ng < 8; ng++) {
                    m0 = fmaxf(m0, fmaxf(acc[rg][ng][0], acc[rg][ng][1]));
                    m1 = fmaxf(m1, fmaxf(acc[rg][ng][2], acc[rg][ng][3]));
                }
                m0 = fmaxf(m0, __shfl_xor_sync(0xffffffffu, m0, 1));
                m0 = fmaxf(m0, __shfl_xor_sync(0xffffffffu, m0, 2));
                m1 = fmaxf(m1, __shfl_xor_sync(0xffffffffu, m1, 1));
                m1 = fmaxf(m1, __shfl_xor_sync(0xffffffffu, m1, 2));
                int r0 = v0 + vb + 16 * rg + lq;
                if (lr == 0) {
                    if (r0 < VV) rsum += m0;
                    if (r0 + 8 < VV) rsum += m1;
                }
            }
            #pragma unroll
            for (int off = 16; off > 0; off >>= 1)
                rsum += __shfl_xor_sync(0xffffffffu, rsum, off);
            i2t_wsum += rsum;

            // ---- t2i: per-t-col max over this warp's 32 v rows (masked) ----
            #pragma unroll
            for (int ng = 0; ng < 8; ng++) {
                float m0 = -1e30f, m1 = -1e30f;
                #pragma unroll
                for (int rg = 0; rg < 2; rg++) {
                    int r0 = v0 + vb + 16 * rg + lq;
                    if (r0 < VV) {
                        m0 = fmaxf(m0, acc[rg][ng][0]);
                        m1 = fmaxf(m1, acc[rg][ng][1]);
                    }
                    if (r0 + 8 < VV) {
                        m0 = fmaxf(m0, acc[rg][ng][2]);
                        m1 = fmaxf(m1, acc[rg][ng][3]);
                    }
                }
                m0 = fmaxf(m0, __shfl_xor_sync(0xffffffffu, m0, 4));
                m0 = fmaxf(m0, __shfl_xor_sync(0xffffffffu, m0, 8));
                m0 = fmaxf(m0, __shfl_xor_sync(0xffffffffu, m0, 16));
                m1 = fmaxf(m1, __shfl_xor_sync(0xffffffffu, m1, 4));
                m1 = fmaxf(m1, __shfl_xor_sync(0xffffffffu, m1, 8));
                m1 = fmaxf(m1, __shfl_xor_sync(0xffffffffu, m1, 16));
                if (lane < 4) {
                    t2i_part[w >> 1][tb + 8 * ng + 2 * lane] = m0;
                    t2i_part[w >> 1][tb + 8 * ng + 2 * lane + 1] = m1;
                }
            }
            __syncthreads();
            if (tid < 128) {
                float m = fmaxf(fmaxf(t2i_part[0][tid], t2i_part[1][tid]),
                                fmaxf(t2i_part[2][tid], t2i_part[3][tid]));
                t2i_run[tid] = (v0 == 0) ? m : fmaxf(t2i_run[tid], m);
            }
            __syncthreads();
        }
    }

    if (lane == 0) wsum[w] = i2t_wsum;
    __syncthreads();

    // t2i outputs: warp 0 -> q0, warp 1 -> q1
    if (tid < 64) {
        int w2 = tid >> 5;
        int l2 = tid & 31;
        int len = text_length[b];   // reference quirk: indexed by b
        float s = 0.0f;
        if (l2 < len) s += t2i_run[w2 * 64 + l2];
        if (l2 + 32 < len) s += t2i_run[w2 * 64 + l2 + 32];
        #pragma unroll
        for (int off = 16; off > 0; off >>= 1)
            s += __shfl_xor_sync(0xffffffffu, s, off);
        if (l2 == 0)
            out[36864 + b * 64 + qp * 2 + w2] = s / fmaxf((float)len, 1e-6f);
    }
    // i2t outputs
    if (tid == 128 || tid == 129) {
        int j = tid - 128;
        float s = wsum[j] + wsum[j + 2] + wsum[j + 4] + wsum[j + 6];
        out[32768 + b * 64 + qp * 2 + j] = s / (float)VV;
    }
}

// ---------------------------------------------------------------------------
extern "C" void kernel_launch(void* const* d_in, const int* in_sizes, int n_in,
                              void* d_out, int out_size)
{
    const float* visual_cls     = (const float*)d_in[0];
    const float* textual_cls    = (const float*)d_in[1];
    const float* visual_tokens  = (const float*)d_in[2];
    const float* textual_tokens = (const float*)d_in[3];
    const int*   text_length    = (const int*)  d_in[4];
    const float* Wv  = (const float*)d_in[5];
    const float* bv  = (const float*)d_in[6];
    const float* Wt  = (const float*)d_in[7];
    const float* bt  = (const float*)d_in[8];
    const float* Wvt = (const float*)d_in[9];
    const float* bvt = (const float*)d_in[10];
    const float* Wtt = (const float*)d_in[11];
    const float* btt = (const float*)d_in[12];
    float* out = (float*)d_out;

    __half *vtok, *ttok, *wvtT, *wttT;
    cudaGetSymbolAddress((void**)&vtok, g_vtok);
    cudaGetSymbolAddress((void**)&ttok, g_ttok);
    cudaGetSymbolAddress((void**)&wvtT, g_wvtT);
    cudaGetSymbolAddress((void**)&wttT, g_wttT);

    const int proj_smem = (64 * 136 + 256 * 136) * sizeof(__half);        // 87040
    const int sim_smem  = (128 * SVS + 128 * STS) * sizeof(__half);       // 102400
    cudaFuncSetAttribute(proj_kernel, cudaFuncAttributeMaxDynamicSharedMemorySize, proj_smem);
    cudaFuncSetAttribute(sim_kernel,  cudaFuncAttributeMaxDynamicSharedMemorySize, sim_smem);

    wprep_kernel<<<dim3(24, 8, 2), dim3(32, 8)>>>(Wvt, Wtt, wvtT, wttT);

    // proj: programmatic dependent launch on wprep
    {
        cudaLaunchAttribute attr[1];
        attr[0].id = cudaLaunchAttributeProgrammaticStreamSerialization;
        attr[0].val.programmaticStreamSerializationAllowed = 1;
        cudaLaunchConfig_t cfg = {};
        cfg.gridDim = dim3(263, 1, 1);
        cfg.blockDim = dim3(256, 1, 1);
        cfg.dynamicSmemBytes = proj_smem;
        cfg.stream = 0;
        cfg.attrs = attr;
        cfg.numAttrs = 1;
        cudaLaunchKernelEx(&cfg, proj_kernel,
            visual_cls, textual_cls, visual_tokens, textual_tokens,
            bv, bt, bvt, btt,
            (const __half*)wvtT, (const __half*)wttT,
            Wv, Wt,
            out, vtok, ttok);
    }

    // sim: programmatic dependent launch on proj
    {
        cudaLaunchAttribute attr[1];
        attr[0].id = cudaLaunchAttributeProgrammaticStreamSerialization;
        attr[0].val.programmaticStreamSerializationAllowed = 1;
        cudaLaunchConfig_t cfg = {};
        cfg.gridDim = dim3(32, 64, 1);
        cfg.blockDim = dim3(256, 1, 1);
        cfg.dynamicSmemBytes = sim_smem;
        cfg.stream = 0;
        cfg.attrs = attr;
        cfg.numAttrs = 1;
        cudaLaunchKernelEx(&cfg, sim_kernel,
            (const __half*)vtok, (const __half*)ttok, text_length, out);
    }
}

// round 17
// speedup vs baseline: 1.0405x; 1.0405x over previous
#include <cuda_runtime.h>
#include <cuda_fp16.h>
#include <math.h>
#include <stdint.h>

#define BB 64
#define VV 197
#define LL 64
#define DD 768
#define EE 256

// Scratch: projected + normalized tokens in fp16, transposed half weights
__device__ __align__(16) __half g_vtok[(size_t)BB * VV * EE]; // 6.45 MB
__device__ __align__(16) __half g_ttok[(size_t)BB * LL * EE]; // 2.1 MB
__device__ __align__(16) __half g_wvtT[(size_t)EE * DD];      // [n][k]
__device__ __align__(16) __half g_wttT[(size_t)EE * DD];
__device__ __align__(16) __half g_wvT[(size_t)EE * DD];
__device__ __align__(16) __half g_wtT[(size_t)EE * DD];

// ---------------------------------------------------------------------------
// helpers
// ---------------------------------------------------------------------------
__device__ __forceinline__ void mma16(float* c, unsigned a0, unsigned a1, unsigned a2,
                                      unsigned a3, unsigned b0, unsigned b1) {
    asm volatile(
        "mma.sync.aligned.m16n8k16.row.col.f32.f16.f16.f32 "
        "{%0,%1,%2,%3},{%4,%5,%6,%7},{%8,%9},{%0,%1,%2,%3};\n"
        : "+f"(c[0]), "+f"(c[1]), "+f"(c[2]), "+f"(c[3])
        : "r"(a0), "r"(a1), "r"(a2), "r"(a3), "r"(b0), "r"(b1));
}

__device__ __forceinline__ void cpa16(unsigned s, const void* g) {
    asm volatile("cp.async.cg.shared.global [%0], [%1], 16;" :: "r"(s), "l"(g) : "memory");
}
__device__ __forceinline__ void cpa_commit() {
    asm volatile("cp.async.commit_group;" ::: "memory");
}
__device__ __forceinline__ void cpa_wait0() {
    asm volatile("cp.async.wait_group 0;" ::: "memory");
}
__device__ __forceinline__ unsigned s2u(const void* p) {
    return (unsigned)__cvta_generic_to_shared(p);
}

// ---------------------------------------------------------------------------
// W transpose + fp32->fp16 prepass: W[768][256] -> WT[256][768] half.
// grid (24, 8, 4), block (32, 8). z: 0=Wvt 1=Wtt 2=Wv 3=Wt.
// Triggers PDL early so proj can launch and run its prologue concurrently.
// ---------------------------------------------------------------------------
__global__ void wprep_kernel(const float* __restrict__ Wvt, const float* __restrict__ Wtt,
                             const float* __restrict__ Wv, const float* __restrict__ Wt,
                             __half* __restrict__ WvtT, __half* __restrict__ WttT,
                             __half* __restrict__ WvT, __half* __restrict__ WtT)
{
    cudaTriggerProgrammaticLaunchCompletion();

    __shared__ float t[32][33];
    const float* W;
    __half* WT;
    switch (blockIdx.z) {
        case 0: W = Wvt; WT = WvtT; break;
        case 1: W = Wtt; WT = WttT; break;
        case 2: W = Wv;  WT = WvT;  break;
        default: W = Wt; WT = WtT;  break;
    }
    int kb = blockIdx.x * 32, nb = blockIdx.y * 32;
    int tx = threadIdx.x, ty = threadIdx.y;
    #pragma unroll
    for (int j = 0; j < 4; j++)
        t[ty + 8 * j][tx] = W[(size_t)(kb + ty + 8 * j) * EE + nb + tx];
    __syncthreads();
    #pragma unroll
    for (int j = 0; j < 4; j++)
        WT[(size_t)(nb + ty + 8 * j) * DD + kb + tx] = __float2half(t[tx][ty + 8 * j]);
}

// ---------------------------------------------------------------------------
// Unified projection (fp16 MMA m16n8k16, fp32 accum), 2 blocks/SM.
// One block = 64 rows x 256 cols, K=768 in chunks of 128.
// PDL: prefills A chunk 0 (input tokens only), then grid-dep-syncs on wprep
// before the first W cp.async. Triggers early so sim can get resident.
// Grid: [0,197) vtok (+bias+l2norm, half out), [197,261) ttok (same),
//       261 vcls (+bias, fp32 out), 262 tcls (+bias, fp32 out).
// ---------------------------------------------------------------------------
__global__ __launch_bounds__(256, 2) void proj_kernel(
    const float* __restrict__ visual_cls, const float* __restrict__ textual_cls,
    const float* __restrict__ vtokA, const float* __restrict__ ttokA,
    const float* __restrict__ bv, const float* __restrict__ bt,
    const float* __restrict__ bvt, const float* __restrict__ btt,
    const __half* __restrict__ WvtT, const __half* __restrict__ WttT,
    const __half* __restrict__ WvT, const __half* __restrict__ WtT,
    float* __restrict__ out, __half* __restrict__ vtokC, __half* __restrict__ ttokC)
{
    cudaTriggerProgrammaticLaunchCompletion();

    extern __shared__ float sm[];
    __shared__ float sbias[256];
    __shared__ float rowsq[64 * 5];
    __shared__ float sinv[64];

    __half* sAh = (__half*)sm;               // 64 x 136
    __half* sWh = (__half*)sm + 64 * 136;    // 256 x 136

    const int bid = blockIdx.x;

    const float* A;
    const __half* WT;
    const float* bias;
    __half* C = nullptr;
    float* Cf = nullptr;
    int mbase = 0;
    bool do_norm;
    if (bid < 197)      { A = vtokA;       WT = WvtT; bias = bvt; C = vtokC; mbase = bid * 64;        do_norm = true;  }
    else if (bid < 261) { A = ttokA;       WT = WttT; bias = btt; C = ttokC; mbase = (bid - 197) * 64; do_norm = true;  }
    else if (bid == 261){ A = visual_cls;  WT = WvT;  bias = bv;  Cf = out;              do_norm = false; }
    else                { A = textual_cls; WT = WtT;  bias = bt;  Cf = out + 16384;      do_norm = false; }

    const int tid = threadIdx.x;
    const int lane = tid & 31, w = tid >> 5;
    const int lq = lane >> 2, lr = lane & 3;
    const int vg = w >> 2, nw = w & 3;
    const int rbase = vg * 32;
    const int nb = nw * 64;

    sbias[tid] = bias[tid];

    const unsigned sWu = s2u(sWh);

    // Prefill A chunk 0 (reads only input tokens — independent of wprep)
    #pragma unroll
    for (int it = 0; it < 8; it++) {
        int idx = tid + it * 256;        // 0..2047
        int r = idx >> 5;                // 0..63
        int c4 = idx & 31;               // float4 unit along k
        float4 v = *(const float4*)(A + (size_t)(mbase + r) * DD + c4 * 4);
        __half2 h0 = __floats2half2_rn(v.x, v.y);
        __half2 h1 = __floats2half2_rn(v.z, v.w);
        uint2 pk = make_uint2(*(unsigned*)&h0, *(unsigned*)&h1);
        *(uint2*)(sAh + r * 136 + c4 * 4) = pk;
    }

    // Wait for wprep's WT to be complete + visible
    cudaGridDependencySynchronize();

    float acc[2][8][4] = {};

    for (int k0 = 0; k0 < DD; k0 += 128) {
        // W chunk: 256 n-rows x 128 k halves via cp.async (16 x 16B per row)
        #pragma unroll
        for (int it = 0; it < 16; it++) {
            int idx = tid + it * 256;        // 0..4095
            int r = idx >> 4;                // 0..255
            int c16 = idx & 15;              // 16-byte chunk (8 halves)
            cpa16(sWu + (unsigned)(r * 136 + c16 * 8) * 2,
                  WT + (size_t)r * DD + k0 + c16 * 8);
        }
        cpa_commit();
        // A chunk: 64 rows x 128 k, fp32 -> half in-register (chunk 0 prefilled)
        if (k0 > 0) {
            #pragma unroll
            for (int it = 0; it < 8; it++) {
                int idx = tid + it * 256;        // 0..2047
                int r = idx >> 5;                // 0..63
                int c4 = idx & 31;               // float4 unit along k
                float4 v = *(const float4*)(A + (size_t)(mbase + r) * DD + k0 + c4 * 4);
                __half2 h0 = __floats2half2_rn(v.x, v.y);
                __half2 h1 = __floats2half2_rn(v.z, v.w);
                uint2 pk = make_uint2(*(unsigned*)&h0, *(unsigned*)&h1);
                *(uint2*)(sAh + r * 136 + c4 * 4) = pk;
            }
        }
        cpa_wait0();
        __syncthreads();

        #pragma unroll
        for (int ks = 0; ks < 8; ks++) {
            unsigned b0[8], b1[8];
            #pragma unroll
            for (int ng = 0; ng < 8; ng++) {
                const __half* p = sWh + (nb + 8 * ng + lq) * 136 + ks * 16 + 2 * lr;
                b0[ng] = *(const unsigned*)p;
                b1[ng] = *(const unsigned*)(p + 8);
            }
            #pragma unroll
            for (int rg = 0; rg < 2; rg++) {
                const __half* p = sAh + (rbase + 16 * rg + lq) * 136 + ks * 16 + 2 * lr;
                unsigned a0 = *(const unsigned*)p;
                unsigned a1 = *(const unsigned*)(p + 8 * 136);
                unsigned a2 = *(const unsigned*)(p + 8);
                unsigned a3 = *(const unsigned*)(p + 8 * 136 + 8);
                #pragma unroll
                for (int ng = 0; ng < 8; ng++)
                    mma16(acc[rg][ng], a0, a1, a2, a3, b0[ng], b1[ng]);
            }
        }
        __syncthreads();
    }

    // bias
    #pragma unroll
    for (int rg = 0; rg < 2; rg++)
        #pragma unroll
        for (int ng = 0; ng < 8; ng++) {
            int col = nb + 8 * ng + 2 * lr;
            float c0 = sbias[col], c1 = sbias[col + 1];
            acc[rg][ng][0] += c0; acc[rg][ng][1] += c1;
            acc[rg][ng][2] += c0; acc[rg][ng][3] += c1;
        }

    if (!do_norm) {
        #pragma unroll
        for (int rg = 0; rg < 2; rg++) {
            int r0 = rbase + 16 * rg + lq;
            #pragma unroll
            for (int ng = 0; ng < 8; ng++) {
                int col = nb + 8 * ng + 2 * lr;
                *(float2*)(Cf + (size_t)r0 * EE + col) =
                    make_float2(acc[rg][ng][0], acc[rg][ng][1]);
                *(float2*)(Cf + (size_t)(r0 + 8) * EE + col) =
                    make_float2(acc[rg][ng][2], acc[rg][ng][3]);
            }
        }
        return;
    }

    // l2norm: per-row sum of squares
    #pragma unroll
    for (int rg = 0; rg < 2; rg++) {
        float s0 = 0.f, s1 = 0.f;
        #pragma unroll
        for (int ng = 0; ng < 8; ng++) {
            s0 += acc[rg][ng][0] * acc[rg][ng][0] + acc[rg][ng][1] * acc[rg][ng][1];
            s1 += acc[rg][ng][2] * acc[rg][ng][2] + acc[rg][ng][3] * acc[rg][ng][3];
        }
        s0 += __shfl_xor_sync(0xffffffffu, s0, 1);
        s0 += __shfl_xor_sync(0xffffffffu, s0, 2);
        s1 += __shfl_xor_sync(0xffffffffu, s1, 1);
        s1 += __shfl_xor_sync(0xffffffffu, s1, 2);
        if (lr == 0) {
            rowsq[(rbase + 16 * rg + lq) * 5 + nw] = s0;
            rowsq[(rbase + 16 * rg + lq + 8) * 5 + nw] = s1;
        }
    }
    __syncthreads();
    if (tid < 64) {
        float s = rowsq[tid * 5] + rowsq[tid * 5 + 1] + rowsq[tid * 5 + 2] + rowsq[tid * 5 + 3];
        sinv[tid] = 1.0f / fmaxf(sqrtf(s), 1e-12f);
    }
    __syncthreads();

    #pragma unroll
    for (int rg = 0; rg < 2; rg++) {
        int r0 = rbase + 16 * rg + lq;
        float inv0 = sinv[r0], inv1 = sinv[r0 + 8];
        #pragma unroll
        for (int ng = 0; ng < 8; ng++) {
            int col = nb + 8 * ng + 2 * lr;
            __half2 h0 = __floats2half2_rn(acc[rg][ng][0] * inv0, acc[rg][ng][1] * inv0);
            __half2 h1 = __floats2half2_rn(acc[rg][ng][2] * inv1, acc[rg][ng][3] * inv1);
            *(__half2*)(C + (size_t)(mbase + r0) * EE + col) = h0;
            *(__half2*)(C + (size_t)(mbase + r0 + 8) * EE + col) = h1;
        }
    }
}

// ---------------------------------------------------------------------------
// Fused sim kernel (fp16 MMA m16n8k16, f32 accum).
// grid = (qpair=32, b=64), 256 threads (8 warps = 4 v-groups x 2 t-groups).
// PDL: grid-dep-syncs on proj before touching vtok/ttok. Block tile
// 128v x 128t; sT resident for K=256; sV streamed as 4 chunks with
// lookahead cp.async; m16 padding elision (rows issued 208 of 197 valid).
// ---------------------------------------------------------------------------
#define SVS 136
#define STS 264

__global__ __launch_bounds__(256, 2) void sim_kernel(
    const __half* __restrict__ vtok, const __half* __restrict__ ttok,
    const int* __restrict__ text_length, float* __restrict__ out)
{
    extern __shared__ __half smh[];
    __half* sV = smh;                  // 128 x SVS
    __half* sT = smh + 128 * SVS;      // 128 x STS (full K)

    __shared__ float t2i_part[4][128];
    __shared__ float t2i_run[128];
    __shared__ float wsum[8];

    const int tid = threadIdx.x;
    const int lane = tid & 31, w = tid >> 5;
    const int lq = lane >> 2, lr = lane & 3;
    const int vb = (w >> 1) * 32;
    const int tb = (w & 1) * 64;
    const int qp = blockIdx.x, b = blockIdx.y;

    const __half* vbase = vtok + (size_t)b * VV * EE;
    const __half* tbase = ttok + (size_t)(qp * 2) * LL * EE;

    unsigned sVu = (unsigned)__cvta_generic_to_shared(sV);
    unsigned sTu = (unsigned)__cvta_generic_to_shared(sT);

    // Wait for proj's vtok/ttok to be complete + visible
    cudaGridDependencySynchronize();

    // sT: full 128 t-rows x 256 k (once per block) + sV chunk 0
    #pragma unroll
    for (int it = 0; it < 16; it++) {
        int idx = tid + it * 256;
        int r = idx >> 5;
        int c8 = idx & 31;
        cpa16(sTu + (unsigned)(r * STS + c8 * 8) * 2, tbase + (size_t)r * EE + c8 * 8);
    }
    #pragma unroll
    for (int it = 0; it < 8; it++) {
        int idx = tid + it * 256;
        int r = idx >> 4;
        int c8 = idx & 15;
        int vr = min(r, VV - 1);
        cpa16(sVu + (unsigned)(r * SVS + c8 * 8) * 2,
              vbase + (size_t)vr * EE + c8 * 8);
    }
    cpa_commit();

    float i2t_wsum = 0.0f;
    float acc[2][8][4];

    #pragma unroll
    for (int c = 0; c < 4; ++c) {
        const int pass = c >> 1, kc = c & 1;
        const int v0 = pass * 128;
        const bool active = (v0 + vb) < VV;
        const bool rgok0 = (v0 + vb) < VV;
        const bool rgok1 = (v0 + vb + 16) < VV;

        if (kc == 0) {
            #pragma unroll
            for (int rg = 0; rg < 2; rg++)
                #pragma unroll
                for (int ng = 0; ng < 8; ng++)
                    #pragma unroll
                    for (int j = 0; j < 4; j++) acc[rg][ng][j] = 0.0f;
        }

        cpa_wait0();
        __syncthreads();

        if (active) {
            #pragma unroll
            for (int ks = 0; ks < 8; ks++) {
                unsigned b0[8], b1[8];
                #pragma unroll
                for (int ng = 0; ng < 8; ng++) {
                    const __half* p = sT + (tb + 8 * ng + lq) * STS + kc * 128 + ks * 16 + 2 * lr;
                    b0[ng] = *(const unsigned*)p;
                    b1[ng] = *(const unsigned*)(p + 8);
                }
                #pragma unroll
                for (int rg = 0; rg < 2; rg++) {
                    if (rg == 0 ? rgok0 : rgok1) {
                        const __half* p = sV + (vb + 16 * rg + lq) * SVS + ks * 16 + 2 * lr;
                        unsigned a0 = *(const unsigned*)p;
                        unsigned a1 = *(const unsigned*)(p + 8 * SVS);
                        unsigned a2 = *(const unsigned*)(p + 8);
                        unsigned a3 = *(const unsigned*)(p + 8 * SVS + 8);
                        #pragma unroll
                        for (int ng = 0; ng < 8; ng++)
                            mma16(acc[rg][ng], a0, a1, a2, a3, b0[ng], b1[ng]);
                    }
                }
            }
        }
        __syncthreads();   // MMAs done block-wide -> sV free for next chunk

        // lookahead: issue next chunk's sV loads
        if (c < 3) {
            const int nc = c + 1;
            const int np = nc >> 1, nkc = nc & 1;
            const int nv0 = np * 128;
            const int itmax = (np == 0) ? 8 : 5;
            for (int it = 0; it < itmax; it++) {
                int idx = tid + it * 256;
                int r = idx >> 4;
                int c8 = idx & 15;
                int vr = min(nv0 + r, VV - 1);
                cpa16(sVu + (unsigned)(r * SVS + c8 * 8) * 2,
                      vbase + (size_t)vr * EE + nkc * 128 + c8 * 8);
            }
            cpa_commit();
        }

        if (kc == 1) {
            // ---- i2t: per-v-row max over this warp's 64 t cols ----
            float rsum = 0.0f;
            #pragma unroll
            for (int rg = 0; rg < 2; rg++) {
                float m0 = -1e30f, m1 = -1e30f;
                #pragma unroll
                for (int ng = 0; ng < 8; ng++) {
                    m0 = fmaxf(m0, fmaxf(acc[rg][ng][0], acc[rg][ng][1]));
                    m1 = fmaxf(m1, fmaxf(acc[rg][ng][2], acc[rg][ng][3]));
                }
                m0 = fmaxf(m0, __shfl_xor_sync(0xffffffffu, m0, 1));
                m0 = fmaxf(m0, __shfl_xor_sync(0xffffffffu, m0, 2));
                m1 = fmaxf(m1, __shfl_xor_sync(0xffffffffu, m1, 1));
                m1 = fmaxf(m1, __shfl_xor_sync(0xffffffffu, m1, 2));
                int r0 = v0 + vb + 16 * rg + lq;
                if (lr == 0) {
                    if (r0 < VV) rsum += m0;
                    if (r0 + 8 < VV) rsum += m1;
                }
            }
            #pragma unroll
            for (int off = 16; off > 0; off >>= 1)
                rsum += __shfl_xor_sync(0xffffffffu, rsum, off);
            i2t_wsum += rsum;

            // ---- t2i: per-t-col max over this warp's 32 v rows (masked) ----
            #pragma unroll
            for (int ng = 0; ng < 8; ng++) {
                float m0 = -1e30f, m1 = -1e30f;
                #pragma unroll
                for (int rg = 0; rg < 2; rg++) {
                    int r0 = v0 + vb + 16 * rg + lq;
                    if (r0 < VV) {
                        m0 = fmaxf(m0, acc[rg][ng][0]);
                        m1 = fmaxf(m1, acc[rg][ng][1]);
                    }
                    if (r0 + 8 < VV) {
                        m0 = fmaxf(m0, acc[rg][ng][2]);
                        m1 = fmaxf(m1, acc[rg][ng][3]);
                    }
                }
                m0 = fmaxf(m0, __shfl_xor_sync(0xffffffffu, m0, 4));
                m0 = fmaxf(m0, __shfl_xor_sync(0xffffffffu, m0, 8));
                m0 = fmaxf(m0, __shfl_xor_sync(0xffffffffu, m0, 16));
                m1 = fmaxf(m1, __shfl_xor_sync(0xffffffffu, m1, 4));
                m1 = fmaxf(m1, __shfl_xor_sync(0xffffffffu, m1, 8));
                m1 = fmaxf(m1, __shfl_xor_sync(0xffffffffu, m1, 16));
                if (lane < 4) {
                    t2i_part[w >> 1][tb + 8 * ng + 2 * lane] = m0;
                    t2i_part[w >> 1][tb + 8 * ng + 2 * lane + 1] = m1;
                }
            }
            __syncthreads();
            if (tid < 128) {
                float m = fmaxf(fmaxf(t2i_part[0][tid], t2i_part[1][tid]),
                                fmaxf(t2i_part[2][tid], t2i_part[3][tid]));
                t2i_run[tid] = (v0 == 0) ? m : fmaxf(t2i_run[tid], m);
            }
            __syncthreads();
        }
    }

    if (lane == 0) wsum[w] = i2t_wsum;
    __syncthreads();

    // t2i outputs: warp 0 -> q0, warp 1 -> q1
    if (tid < 64) {
        int w2 = tid >> 5;
        int l2 = tid & 31;
        int len = text_length[b];   // reference quirk: indexed by b
        float s = 0.0f;
        if (l2 < len) s += t2i_run[w2 * 64 + l2];
        if (l2 + 32 < len) s += t2i_run[w2 * 64 + l2 + 32];
        #pragma unroll
        for (int off = 16; off > 0; off >>= 1)
            s += __shfl_xor_sync(0xffffffffu, s, off);
        if (l2 == 0)
            out[36864 + b * 64 + qp * 2 + w2] = s / fmaxf((float)len, 1e-6f);
    }
    // i2t outputs
    if (tid == 128 || tid == 129) {
        int j = tid - 128;
        float s = wsum[j] + wsum[j + 2] + wsum[j + 4] + wsum[j + 6];
        out[32768 + b * 64 + qp * 2 + j] = s / (float)VV;
    }
}

// ---------------------------------------------------------------------------
extern "C" void kernel_launch(void* const* d_in, const int* in_sizes, int n_in,
                              void* d_out, int out_size)
{
    const float* visual_cls     = (const float*)d_in[0];
    const float* textual_cls    = (const float*)d_in[1];
    const float* visual_tokens  = (const float*)d_in[2];
    const float* textual_tokens = (const float*)d_in[3];
    const int*   text_length    = (const int*)  d_in[4];
    const float* Wv  = (const float*)d_in[5];
    const float* bv  = (const float*)d_in[6];
    const float* Wt  = (const float*)d_in[7];
    const float* bt  = (const float*)d_in[8];
    const float* Wvt = (const float*)d_in[9];
    const float* bvt = (const float*)d_in[10];
    const float* Wtt = (const float*)d_in[11];
    const float* btt = (const float*)d_in[12];
    float* out = (float*)d_out;

    __half *vtok, *ttok, *wvtT, *wttT, *wvT, *wtT;
    cudaGetSymbolAddress((void**)&vtok, g_vtok);
    cudaGetSymbolAddress((void**)&ttok, g_ttok);
    cudaGetSymbolAddress((void**)&wvtT, g_wvtT);
    cudaGetSymbolAddress((void**)&wttT, g_wttT);
    cudaGetSymbolAddress((void**)&wvT, g_wvT);
    cudaGetSymbolAddress((void**)&wtT, g_wtT);

    const int proj_smem = (64 * 136 + 256 * 136) * sizeof(__half);        // 87040
    const int sim_smem  = (128 * SVS + 128 * STS) * sizeof(__half);       // 102400
    cudaFuncSetAttribute(proj_kernel, cudaFuncAttributeMaxDynamicSharedMemorySize, proj_smem);
    cudaFuncSetAttribute(sim_kernel,  cudaFuncAttributeMaxDynamicSharedMemorySize, sim_smem);

    wprep_kernel<<<dim3(24, 8, 4), dim3(32, 8)>>>(Wvt, Wtt, Wv, Wt, wvtT, wttT, wvT, wtT);

    // proj: programmatic dependent launch on wprep
    {
        cudaLaunchAttribute attr[1];
        attr[0].id = cudaLaunchAttributeProgrammaticStreamSerialization;
        attr[0].val.programmaticStreamSerializationAllowed = 1;
        cudaLaunchConfig_t cfg = {};
        cfg.gridDim = dim3(263, 1, 1);
        cfg.blockDim = dim3(256, 1, 1);
        cfg.dynamicSmemBytes = proj_smem;
        cfg.stream = 0;
        cfg.attrs = attr;
        cfg.numAttrs = 1;
        cudaLaunchKernelEx(&cfg, proj_kernel,
            visual_cls, textual_cls, visual_tokens, textual_tokens,
            bv, bt, bvt, btt,
            (const __half*)wvtT, (const __half*)wttT,
            (const __half*)wvT, (const __half*)wtT,
            out, vtok, ttok);
    }

    // sim: programmatic dependent launch on proj
    {
        cudaLaunchAttribute attr[1];
        attr[0].id = cudaLaunchAttributeProgrammaticStreamSerialization;
        attr[0].val.programmaticStreamSerializationAllowed = 1;
        cudaLaunchConfig_t cfg = {};
        cfg.gridDim = dim3(32, 64, 1);
        cfg.blockDim = dim3(256, 1, 1);
        cfg.dynamicSmemBytes = sim_smem;
        cfg.stream = 0;
        cfg.attrs = attr;
        cfg.numAttrs = 1;
        cudaLaunchKernelEx(&cfg, sim_kernel,
            (const __half*)vtok, (const __half*)ttok, text_length, out);
    }
}